// round 10
// baseline (speedup 1.0000x reference)
#include <cuda_runtime.h>
#include <math.h>

#define D      128
#define RREL   500
#define NNODES 200000
#define ZB     148          // total blocks in k_pre (block 0 = chain, rest zero)

// ---------------- device scratch ----------------
__device__ float2 g_acc[NNODES];
__device__ float  g_bdot[4];
__device__ float  g_ceff;
__device__ float  g_udot[RREL * 4];
__device__ float  g_reldot[RREL];

__device__ __forceinline__ float warp_sum(float v) {
#pragma unroll
    for (int o = 16; o > 0; o >>= 1) v += __shfl_down_sync(0xffffffffu, v, o);
    return v;
}

// ---------------- K1: block 0 computes full scalar chain; others zero g_acc ----
__global__ void __launch_bounds__(1024)
k_pre(const float* __restrict__ rel_emb,
      const float* __restrict__ W_hh, const float* __restrict__ b_hh,
      const float* __restrict__ W_ht, const float* __restrict__ b_ht,
      const float* __restrict__ W_th, const float* __restrict__ b_th,
      const float* __restrict__ W_tt, const float* __restrict__ b_tt,
      const float* __restrict__ W_fin, const float* __restrict__ b_fin,
      const float* __restrict__ W_score, const float* __restrict__ b_score) {
    if (blockIdx.x != 0) {
        // zero g_acc across blocks 1..ZB-1
        int nt = (ZB - 1) * 1024;
        for (int i = (blockIdx.x - 1) * 1024 + threadIdx.x; i < NNODES; i += nt)
            g_acc[i] = make_float2(0.f, 0.f);
        return;
    }

    // ---- block 0: the whole chain with block-level syncs ----
    __shared__ float s_ws[D];        // W_score
    __shared__ float s_w1[D];        // w_eff upper
    __shared__ float s_w2[D];        // w_eff lower
    __shared__ float s_p[4][D];      // W_x @ w1

    const int tid  = threadIdx.x;
    const int lane = tid & 31;
    const int wid  = tid >> 5;       // 0..31

    if (tid < D) s_ws[tid] = W_score[tid];
    __syncthreads();

    // stage A: w_eff rows (256 rows over 32 warps -> 8 rows each), ceff, bdot
    {
        float wsv[4];
#pragma unroll
        for (int i = 0; i < 4; i++) wsv[i] = s_ws[lane + 32 * i];
#pragma unroll
        for (int rr = 0; rr < 8; rr++) {
            int row = wid * 8 + rr;
            const float* Wr = W_fin + row * D;
            float v = 0.f;
#pragma unroll
            for (int i = 0; i < 4; i++) v += Wr[lane + 32 * i] * wsv[i];
            v = warp_sum(v);
            if (lane == 0) { if (row < D) s_w1[row] = v; else s_w2[row - D] = v; }
        }
        if (wid == 0) {   // ceff
            float v = 0.f;
#pragma unroll
            for (int i = 0; i < 4; i++) v += b_fin[lane + 32 * i] * wsv[i];
            v = warp_sum(v);
            if (lane == 0) g_ceff = v + b_score[0];
        }
    }
    __syncthreads();

    // stage B: p_x rows (512 over 32 warps -> 16 each) + bdot (warps 0..3)
    {
        float w1v[4];
#pragma unroll
        for (int i = 0; i < 4; i++) w1v[i] = s_w1[lane + 32 * i];
        const float* Ws[4] = {W_hh, W_ht, W_th, W_tt};
#pragma unroll
        for (int rr = 0; rr < 16; rr++) {
            int row = wid * 16 + rr;            // 0..511
            int x = row >> 7, k = row & (D - 1);
            const float* Wr = Ws[x] + k * D;
            float v = 0.f;
#pragma unroll
            for (int i = 0; i < 4; i++) v += Wr[lane + 32 * i] * w1v[i];
            v = warp_sum(v);
            if (lane == 0) s_p[x][k] = v;
        }
        if (wid < 4) {
            const float* bs[4] = {b_hh, b_ht, b_th, b_tt};
            float v = 0.f;
#pragma unroll
            for (int i = 0; i < 4; i++) v += bs[wid][lane + 32 * i] * w1v[i];
            v = warp_sum(v);
            if (lane == 0) g_bdot[wid] = v;
        }
    }
    __syncthreads();

    // stage C: udot / reldot (500 relations over 32 warps -> ceil 16 each)
    {
        float pv[4][4], w2v[4];
#pragma unroll
        for (int i = 0; i < 4; i++) {
            w2v[i] = s_w2[lane + 32 * i];
#pragma unroll
            for (int x = 0; x < 4; x++) pv[x][i] = s_p[x][lane + 32 * i];
        }
        for (int r = wid; r < RREL; r += 32) {
            const float* er = rel_emb + r * D;
            float e[4];
#pragma unroll
            for (int i = 0; i < 4; i++) e[i] = er[lane + 32 * i];
            float acc[5] = {0.f, 0.f, 0.f, 0.f, 0.f};
#pragma unroll
            for (int i = 0; i < 4; i++) {
#pragma unroll
                for (int x = 0; x < 4; x++) acc[x] += e[i] * pv[x][i];
                acc[4] += e[i] * w2v[i];
            }
#pragma unroll
            for (int x = 0; x < 5; x++) acc[x] = warp_sum(acc[x]);
            if (lane == 0) {
#pragma unroll
                for (int x = 0; x < 4; x++) g_udot[r * 4 + x] = acc[x];
                g_reldot[r] = acc[4];
            }
        }
    }
}

// ---------------- K2: edges, 2 per thread, front-batched ----------------
__global__ void __launch_bounds__(256)
k_edge(const int* __restrict__ ht, const int* __restrict__ r_q,
       const int* __restrict__ r_tensor, const int* __restrict__ r_relative,
       const int* __restrict__ h_or_t, const float* __restrict__ corr,
       int M, int nq) {
    const int g = blockIdx.x * 256 + threadIdx.x;
    const int ngroups = M >> 1;
    if (g < ngroups) {
        int4 ev  = ((const int4*)ht)[g];
        int2 rtv = ((const int2*)r_tensor)[g];
        int2 rqv = ((const int2*)r_q)[g];
        int2 rrv = ((const int2*)r_relative)[g];
        int2 hsv = ((const int2*)h_or_t)[g];
        int hh[2]  = {ev.x, ev.z};
        int tt[2]  = {ev.y, ev.w};
        int rta[2] = {rtv.x, rtv.y};
        int rqa[2] = {rqv.x, rqv.y};
        int rra[2] = {rrv.x, rrv.y};
        int hsa[2] = {hsv.x, hsv.y};
        float cv[2];
#pragma unroll
        for (int j = 0; j < 2; j++) cv[j] = __ldg(&corr[rta[j] * RREL + rqa[j]]);
        int mbase = g << 1;
#pragma unroll
        for (int j = 0; j < 2; j++) {
            float gate = 1.f / (1.f + __expf(-cv[j]));
            int idx = ((rra[j] == 0) ? 2 : 0) + ((hsa[j] == 0) ? 1 : 0);
            float s = gate * g_udot[rta[j] * 4 + idx] + g_bdot[idx];
            if (mbase + j < nq) s = 0.f;   // query edges: count only
            asm volatile("red.global.add.v2.f32 [%0], {%1, %2};"
                         :: "l"(&g_acc[hh[j]]), "f"(s), "f"(1.0f) : "memory");
            asm volatile("red.global.add.v2.f32 [%0], {%1, %2};"
                         :: "l"(&g_acc[tt[j]]), "f"(s), "f"(1.0f) : "memory");
        }
    }
    if ((M & 1) && blockIdx.x == 0 && threadIdx.x == 0) {
        int m = M - 1;
        int2 e = ((const int2*)ht)[m];
        int rt = r_tensor[m], rq = r_q[m];
        float c = corr[rt * RREL + rq];
        float gate = 1.f / (1.f + __expf(-c));
        int idx = ((r_relative[m] == 0) ? 2 : 0) + ((h_or_t[m] == 0) ? 1 : 0);
        float s = gate * g_udot[rt * 4 + idx] + g_bdot[idx];
        if (m < nq) s = 0.f;
        asm volatile("red.global.add.v2.f32 [%0], {%1, %2};"
                     :: "l"(&g_acc[e.x]), "f"(s), "f"(1.0f) : "memory");
        asm volatile("red.global.add.v2.f32 [%0], {%1, %2};"
                     :: "l"(&g_acc[e.y]), "f"(s), "f"(1.0f) : "memory");
    }
}

// ---------------- K3: queries, 2 per thread, front-batched gathers ----------------
__device__ __forceinline__ float2 ldcg_f2(const float2* p) {
    float2 r;
    asm volatile("ld.global.cg.v2.f32 {%0, %1}, [%2];"
                 : "=f"(r.x), "=f"(r.y) : "l"(p));
    return r;
}

__global__ void __launch_bounds__(256)
k_query(const int* __restrict__ ht, const int* __restrict__ r_tensor,
        float* __restrict__ out, int nq) {
    const int g = blockIdx.x * 256 + threadIdx.x;
    const int ngroups = nq >> 1;
    if (g < ngroups) {
        int4 ev  = ((const int4*)ht)[g];
        int2 rtv = ((const int2*)r_tensor)[g];
        int hh[2] = {ev.x, ev.z};
        int tt[2] = {ev.y, ev.w};
        float2 ah[2], at[2];
        float rd[2];
#pragma unroll
        for (int j = 0; j < 2; j++) ah[j] = ldcg_f2(&g_acc[hh[j]]);
#pragma unroll
        for (int j = 0; j < 2; j++) at[j] = ldcg_f2(&g_acc[tt[j]]);
        rd[0] = g_reldot[rtv.x];
        rd[1] = g_reldot[rtv.y];
        float2 o;
        o.x = ah[0].x / fmaxf(ah[0].y, 1.f) + at[0].x / fmaxf(at[0].y, 1.f) + rd[0] + g_ceff;
        o.y = ah[1].x / fmaxf(ah[1].y, 1.f) + at[1].x / fmaxf(at[1].y, 1.f) + rd[1] + g_ceff;
        ((float2*)out)[g] = o;
    }
    if ((nq & 1) && blockIdx.x == 0 && threadIdx.x == 0) {
        int q = nq - 1;
        int2 e = ((const int2*)ht)[q];
        float2 ah = ldcg_f2(&g_acc[e.x]);
        float2 at = ldcg_f2(&g_acc[e.y]);
        out[q] = ah.x / fmaxf(ah.y, 1.f) + at.x / fmaxf(at.y, 1.f)
               + g_reldot[r_tensor[q]] + g_ceff;
    }
}

// ---------------- launch ----------------
extern "C" void kernel_launch(void* const* d_in, const int* in_sizes, int n_in,
                              void* d_out, int out_size) {
    const int* ht         = (const int*)d_in[0];
    const int* r_q        = (const int*)d_in[1];
    const int* r_tensor   = (const int*)d_in[2];
    const int* r_relative = (const int*)d_in[3];
    const int* h_or_t     = (const int*)d_in[4];
    int base = n_in - 14;
    const float* rel_emb = (const float*)d_in[base + 0];
    const float* corr    = (const float*)d_in[base + 1];
    const float* W_hh    = (const float*)d_in[base + 2];
    const float* b_hh    = (const float*)d_in[base + 3];
    const float* W_ht    = (const float*)d_in[base + 4];
    const float* b_ht    = (const float*)d_in[base + 5];
    const float* W_th    = (const float*)d_in[base + 6];
    const float* b_th    = (const float*)d_in[base + 7];
    const float* W_tt    = (const float*)d_in[base + 8];
    const float* b_tt    = (const float*)d_in[base + 9];
    const float* W_fin   = (const float*)d_in[base + 10];
    const float* b_fin   = (const float*)d_in[base + 11];
    const float* W_score = (const float*)d_in[base + 12];
    const float* b_score = (const float*)d_in[base + 13];

    int M  = in_sizes[0] / 2;
    int nq = out_size;

    k_pre<<<ZB, 1024>>>(rel_emb, W_hh, b_hh, W_ht, b_ht, W_th, b_th,
                        W_tt, b_tt, W_fin, b_fin, W_score, b_score);
    int eg = M >> 1;
    k_edge<<<(eg + 255) / 256, 256>>>(ht, r_q, r_tensor, r_relative, h_or_t,
                                      corr, M, nq);
    int qg = nq >> 1;
    k_query<<<(qg + 255) / 256 + (qg == 0), 256>>>(ht, r_tensor, (float*)d_out, nq);
}

// round 11
// speedup vs baseline: 1.6962x; 1.6962x over previous
#include <cuda_runtime.h>
#include <math.h>

#define D      128
#define RREL   500
#define NNODES 200000
#define PREB   33           // k_pre blocks: 33*8 = 264 warps
#define PTPB   256
#define PNT    (PREB * PTPB)

// ---------------- device scratch ----------------
__device__ float2 g_acc[NNODES];
__device__ float  g_w1[D];
__device__ float  g_w2[D];
__device__ float  g_p[4][D];
__device__ float  g_bdot[4];
__device__ float  g_ceff;
__device__ float  g_udot[RREL * 4];
__device__ float  g_reldot[RREL];
__device__ unsigned g_bar;          // monotonic ticket counter (graph-replay safe)

__device__ __forceinline__ float warp_sum(float v) {
#pragma unroll
    for (int o = 16; o > 0; o >>= 1) v += __shfl_down_sync(0xffffffffu, v, o);
    return v;
}

// Monotonic ticket barrier over PREB blocks, nanosleep backoff.
__device__ __forceinline__ void pre_barrier() {
    __syncthreads();
    if (threadIdx.x == 0) {
        __threadfence();
        unsigned old = atomicAdd(&g_bar, 1u);
        unsigned target = old - (old % PREB) + PREB;
        unsigned v;
        do {
            asm volatile("ld.acquire.gpu.u32 %0, [%1];" : "=r"(v) : "l"(&g_bar));
            if (v >= target) break;
            __nanosleep(32);
        } while (true);
    }
    __syncthreads();
}

// ---------------- K1: precompute + zeroing on 33 blocks (2 cheap barriers) ----
__global__ void __launch_bounds__(PTPB)
k_pre(const float* __restrict__ rel_emb,
      const float* __restrict__ W_hh, const float* __restrict__ b_hh,
      const float* __restrict__ W_ht, const float* __restrict__ b_ht,
      const float* __restrict__ W_th, const float* __restrict__ b_th,
      const float* __restrict__ W_tt, const float* __restrict__ b_tt,
      const float* __restrict__ W_fin, const float* __restrict__ b_fin,
      const float* __restrict__ W_score, const float* __restrict__ b_score) {
    const int tid  = threadIdx.x;
    const int gt   = blockIdx.x * PTPB + tid;
    const int lane = tid & 31;
    const int gw   = gt >> 5;       // 0..263

    // stage 0: w_eff (rows 0..255 = warp id), ceff (warp 256); zero g_acc (all)
    if (gw < 256) {
        float v = 0.f;
#pragma unroll
        for (int i = 0; i < 4; i++) {
            int d = lane + 32 * i;
            v += W_fin[gw * D + d] * W_score[d];
        }
        v = warp_sum(v);
        if (lane == 0) { if (gw < D) g_w1[gw] = v; else g_w2[gw - D] = v; }
    } else if (gw == 256) {
        float v = 0.f;
#pragma unroll
        for (int i = 0; i < 4; i++) {
            int d = lane + 32 * i;
            v += b_fin[d] * W_score[d];
        }
        v = warp_sum(v);
        if (lane == 0) g_ceff = v + b_score[0];
    }
    for (int i = gt; i < NNODES; i += PNT) g_acc[i] = make_float2(0.f, 0.f);
    pre_barrier();

    // stage 1: p_x rows 2*gw, 2*gw+1 (gw<256); bdot on warps 256..259
    {
        const float* Ws[4] = {W_hh, W_ht, W_th, W_tt};
        if (gw < 256) {
            float w1v[4];
#pragma unroll
            for (int i = 0; i < 4; i++) w1v[i] = g_w1[lane + 32 * i];
#pragma unroll
            for (int rr = 0; rr < 2; rr++) {
                int row = 2 * gw + rr;          // 0..511
                int x = row >> 7, k = row & (D - 1);
                const float* Wr = Ws[x] + k * D;
                float v = 0.f;
#pragma unroll
                for (int i = 0; i < 4; i++) v += Wr[lane + 32 * i] * w1v[i];
                v = warp_sum(v);
                if (lane == 0) g_p[x][k] = v;
            }
        } else if (gw < 260) {
            const float* bs[4] = {b_hh, b_ht, b_th, b_tt};
            int x = gw - 256;
            float v = 0.f;
#pragma unroll
            for (int i = 0; i < 4; i++) {
                int d = lane + 32 * i;
                v += bs[x][d] * g_w1[d];
            }
            v = warp_sum(v);
            if (lane == 0) g_bdot[x] = v;
        }
    }
    pre_barrier();

    // stage 2: udot / reldot — relations gw and gw+264
#pragma unroll
    for (int half = 0; half < 2; half++) {
        int r = gw + half * 264;
        if (r < RREL) {
            const float* er = rel_emb + r * D;
            float e[4];
#pragma unroll
            for (int i = 0; i < 4; i++) e[i] = er[lane + 32 * i];
            float acc[5] = {0.f, 0.f, 0.f, 0.f, 0.f};
#pragma unroll
            for (int i = 0; i < 4; i++) {
                int d = lane + 32 * i;
#pragma unroll
                for (int x = 0; x < 4; x++) acc[x] += e[i] * g_p[x][d];
                acc[4] += e[i] * g_w2[d];
            }
#pragma unroll
            for (int x = 0; x < 5; x++) acc[x] = warp_sum(acc[x]);
            if (lane == 0) {
#pragma unroll
                for (int x = 0; x < 4; x++) g_udot[r * 4 + x] = acc[x];
                g_reldot[r] = acc[4];
            }
        }
    }
}

// ---------------- K2: edges, 2 per thread, front-batched ----------------
__global__ void __launch_bounds__(256)
k_edge(const int* __restrict__ ht, const int* __restrict__ r_q,
       const int* __restrict__ r_tensor, const int* __restrict__ r_relative,
       const int* __restrict__ h_or_t, const float* __restrict__ corr,
       int M, int nq) {
    const int g = blockIdx.x * 256 + threadIdx.x;
    const int ngroups = M >> 1;
    if (g < ngroups) {
        int4 ev  = ((const int4*)ht)[g];
        int2 rtv = ((const int2*)r_tensor)[g];
        int2 rqv = ((const int2*)r_q)[g];
        int2 rrv = ((const int2*)r_relative)[g];
        int2 hsv = ((const int2*)h_or_t)[g];
        int hh[2]  = {ev.x, ev.z};
        int tt[2]  = {ev.y, ev.w};
        int rta[2] = {rtv.x, rtv.y};
        int rqa[2] = {rqv.x, rqv.y};
        int rra[2] = {rrv.x, rrv.y};
        int hsa[2] = {hsv.x, hsv.y};
        float cv[2];
#pragma unroll
        for (int j = 0; j < 2; j++) cv[j] = __ldg(&corr[rta[j] * RREL + rqa[j]]);
        int mbase = g << 1;
#pragma unroll
        for (int j = 0; j < 2; j++) {
            float gate = 1.f / (1.f + __expf(-cv[j]));
            int idx = ((rra[j] == 0) ? 2 : 0) + ((hsa[j] == 0) ? 1 : 0);
            float s = gate * g_udot[rta[j] * 4 + idx] + g_bdot[idx];
            if (mbase + j < nq) s = 0.f;   // query edges: count only
            asm volatile("red.global.add.v2.f32 [%0], {%1, %2};"
                         :: "l"(&g_acc[hh[j]]), "f"(s), "f"(1.0f) : "memory");
            asm volatile("red.global.add.v2.f32 [%0], {%1, %2};"
                         :: "l"(&g_acc[tt[j]]), "f"(s), "f"(1.0f) : "memory");
        }
    }
    if ((M & 1) && blockIdx.x == 0 && threadIdx.x == 0) {
        int m = M - 1;
        int2 e = ((const int2*)ht)[m];
        int rt = r_tensor[m], rq = r_q[m];
        float c = corr[rt * RREL + rq];
        float gate = 1.f / (1.f + __expf(-c));
        int idx = ((r_relative[m] == 0) ? 2 : 0) + ((h_or_t[m] == 0) ? 1 : 0);
        float s = gate * g_udot[rt * 4 + idx] + g_bdot[idx];
        if (m < nq) s = 0.f;
        asm volatile("red.global.add.v2.f32 [%0], {%1, %2};"
                     :: "l"(&g_acc[e.x]), "f"(s), "f"(1.0f) : "memory");
        asm volatile("red.global.add.v2.f32 [%0], {%1, %2};"
                     :: "l"(&g_acc[e.y]), "f"(s), "f"(1.0f) : "memory");
    }
}

// ---------------- K3: queries, 2 per thread, front-batched gathers ----------------
__device__ __forceinline__ float2 ldcg_f2(const float2* p) {
    float2 r;
    asm volatile("ld.global.cg.v2.f32 {%0, %1}, [%2];"
                 : "=f"(r.x), "=f"(r.y) : "l"(p));
    return r;
}

__global__ void __launch_bounds__(256)
k_query(const int* __restrict__ ht, const int* __restrict__ r_tensor,
        float* __restrict__ out, int nq) {
    const int g = blockIdx.x * 256 + threadIdx.x;
    const int ngroups = nq >> 1;
    if (g < ngroups) {
        int4 ev  = ((const int4*)ht)[g];
        int2 rtv = ((const int2*)r_tensor)[g];
        int hh[2] = {ev.x, ev.z};
        int tt[2] = {ev.y, ev.w};
        float2 ah[2], at[2];
        float rd[2];
#pragma unroll
        for (int j = 0; j < 2; j++) ah[j] = ldcg_f2(&g_acc[hh[j]]);
#pragma unroll
        for (int j = 0; j < 2; j++) at[j] = ldcg_f2(&g_acc[tt[j]]);
        rd[0] = g_reldot[rtv.x];
        rd[1] = g_reldot[rtv.y];
        float2 o;
        o.x = ah[0].x / fmaxf(ah[0].y, 1.f) + at[0].x / fmaxf(at[0].y, 1.f) + rd[0] + g_ceff;
        o.y = ah[1].x / fmaxf(ah[1].y, 1.f) + at[1].x / fmaxf(at[1].y, 1.f) + rd[1] + g_ceff;
        ((float2*)out)[g] = o;
    }
    if ((nq & 1) && blockIdx.x == 0 && threadIdx.x == 0) {
        int q = nq - 1;
        int2 e = ((const int2*)ht)[q];
        float2 ah = ldcg_f2(&g_acc[e.x]);
        float2 at = ldcg_f2(&g_acc[e.y]);
        out[q] = ah.x / fmaxf(ah.y, 1.f) + at.x / fmaxf(at.y, 1.f)
               + g_reldot[r_tensor[q]] + g_ceff;
    }
}

// ---------------- launch ----------------
extern "C" void kernel_launch(void* const* d_in, const int* in_sizes, int n_in,
                              void* d_out, int out_size) {
    const int* ht         = (const int*)d_in[0];
    const int* r_q        = (const int*)d_in[1];
    const int* r_tensor   = (const int*)d_in[2];
    const int* r_relative = (const int*)d_in[3];
    const int* h_or_t     = (const int*)d_in[4];
    int base = n_in - 14;
    const float* rel_emb = (const float*)d_in[base + 0];
    const float* corr    = (const float*)d_in[base + 1];
    const float* W_hh    = (const float*)d_in[base + 2];
    const float* b_hh    = (const float*)d_in[base + 3];
    const float* W_ht    = (const float*)d_in[base + 4];
    const float* b_ht    = (const float*)d_in[base + 5];
    const float* W_th    = (const float*)d_in[base + 6];
    const float* b_th    = (const float*)d_in[base + 7];
    const float* W_tt    = (const float*)d_in[base + 8];
    const float* b_tt    = (const float*)d_in[base + 9];
    const float* W_fin   = (const float*)d_in[base + 10];
    const float* b_fin   = (const float*)d_in[base + 11];
    const float* W_score = (const float*)d_in[base + 12];
    const float* b_score = (const float*)d_in[base + 13];

    int M  = in_sizes[0] / 2;
    int nq = out_size;

    k_pre<<<PREB, PTPB>>>(rel_emb, W_hh, b_hh, W_ht, b_ht, W_th, b_th,
                          W_tt, b_tt, W_fin, b_fin, W_score, b_score);
    int eg = M >> 1;
    k_edge<<<(eg + 255) / 256, 256>>>(ht, r_q, r_tensor, r_relative, h_or_t,
                                      corr, M, nq);
    int qg = nq >> 1;
    k_query<<<(qg + 255) / 256 + (qg == 0), 256>>>(ht, r_tensor, (float*)d_out, nq);
}